// round 1
// baseline (speedup 1.0000x reference)
#include <cuda_runtime.h>

// Problem dims
#define RD 64
#define UD 64
#define VD 64
#define HD 128
#define XD 64
#define NB 8
#define IJ 1024          // 32*32 tokens per batch

// Kernel-B tiling
#define TM 64            // token tile
#define HC 64            // h chunk (HD/2, split across blockIdx.z)
#define TMP (TM + 4)
#define HCP (HC + 4)
#define XDP (XD + 4)

#define SMEM_B ((VD*TMP + RD*TMP + VD*HCP + HC*XDP + HC*TMP) * (int)sizeof(float))

// Scratch: A[n][r][v][h] = sum_u w1[r,u,v,h] * u[n,r,u,v]   (16.8 MB)
__device__ float g_A[NB * RD * VD * HD];

// ---------------------------------------------------------------------------
// Kernel A: contract u-axis.  grid (RD, VD), 128 threads over h.
// w1 is read exactly once (coalesced 512B rows); all 8 batches in registers.
// ---------------------------------------------------------------------------
__global__ __launch_bounds__(128) void kernA(const float* __restrict__ u,
                                             const float* __restrict__ w1) {
    const int rr = blockIdx.x;
    const int vv = blockIdx.y;
    const int h  = threadIdx.x;

    __shared__ float us[NB][UD];
    for (int idx = threadIdx.x; idx < NB * UD; idx += 128) {
        int n = idx >> 6, uu = idx & 63;
        us[n][uu] = u[((n * RD + rr) * UD + uu) * VD + vv];
    }
    __syncthreads();

    float acc[NB];
#pragma unroll
    for (int n = 0; n < NB; n++) acc[n] = 0.f;

    const float* w1p = w1 + (rr * UD * VD + vv) * HD + h;
#pragma unroll 4
    for (int uu = 0; uu < UD; uu++) {
        float w = w1p[uu * (VD * HD)];
#pragma unroll
        for (int n = 0; n < NB; n++) acc[n] = fmaf(w, us[n][uu], acc[n]);
    }
#pragma unroll
    for (int n = 0; n < NB; n++)
        g_A[((n * RD + rr) * VD + vv) * HD + h] = acc[n];
}

// ---------------------------------------------------------------------------
// Zero the output (it is poisoned before timing; kernel B accumulates atomically)
// ---------------------------------------------------------------------------
__global__ void kzero(float* __restrict__ out, int nElem) {
    int i = blockIdx.x * blockDim.x + threadIdx.x;
    if (i < nElem) out[i] = 0.f;
}

// ---------------------------------------------------------------------------
// Kernel B: fused double GEMM per token tile.
//   P[m,h]  = relu( sum_v V[m,v] * A[n,rr,v,h] ) * r[m,rr]
//   OUT[m,x] += sum_h P[m,h] * w2[x,rr,h]
// grid (16 tiles, 8 n, 2 h-halves), 256 threads, 4x4 register micro-tiles.
// ---------------------------------------------------------------------------
extern __shared__ float smem[];

__global__ __launch_bounds__(256, 2) void kernB(const float* __restrict__ v,
                                                const float* __restrict__ r,
                                                const float* __restrict__ w2,
                                                float* __restrict__ out) {
    const int tile   = blockIdx.x;          // 0..15
    const int n      = blockIdx.y;          // 0..7
    const int hblk   = blockIdx.z;          // 0..1
    const int token0 = tile * TM;
    const int tid    = threadIdx.x;
    const int mi = tid >> 4, ni = tid & 15;
    const int m0 = mi * 4, c0 = ni * 4;     // c0 = h offset (stage1) / x offset (stage2)

    float* Vs  = smem;                      // [VD][TMP]  V transposed: [v][m]
    float* Rs  = Vs  + VD * TMP;            // [RD][TMP]  r transposed: [rr][m]
    float* Ach = Rs  + RD * TMP;            // [VD][HCP]  A chunk:      [v][h]
    float* W2T = Ach + VD * HCP;            // [HC][XDP]  w2 transposed:[h][x]
    float* Ps  = W2T + HC * XDP;            // [HC][TMP]  P transposed: [h][m]

    for (int idx = tid; idx < TM * VD; idx += 256) {
        int m = idx >> 6, k = idx & 63;
        Vs[k * TMP + m] = v[(n * IJ + token0 + m) * VD + k];
        Rs[k * TMP + m] = r[(n * IJ + token0 + m) * RD + k];
    }

    float oacc[4][4];
#pragma unroll
    for (int a = 0; a < 4; a++)
#pragma unroll
        for (int b = 0; b < 4; b++) oacc[a][b] = 0.f;

    const int h0g = hblk * HC;

    for (int rr = 0; rr < RD; rr++) {
        __syncthreads();   // previous iter's consumers of Ach/W2T/Ps are done
        {
            const float* Ab = g_A + ((n * RD + rr) * VD) * HD + h0g;
            for (int idx = tid; idx < VD * HC; idx += 256) {
                int k = idx >> 6, hh = idx & 63;
                Ach[k * HCP + hh] = Ab[k * HD + hh];
            }
            const float* Wb = w2 + rr * HD + h0g;
            for (int idx = tid; idx < XD * HC; idx += 256) {
                int x = idx >> 6, hh = idx & 63;
                W2T[hh * XDP + x] = Wb[x * (RD * HD) + hh];
            }
        }
        __syncthreads();

        // ---- stage 1: P tile (64 x HC), K = VD ----
        float p[4][4];
#pragma unroll
        for (int a = 0; a < 4; a++)
#pragma unroll
            for (int b = 0; b < 4; b++) p[a][b] = 0.f;

#pragma unroll 8
        for (int k = 0; k < VD; k++) {
            float4 vm = *(const float4*)&Vs[k * TMP + m0];
            float4 va = *(const float4*)&Ach[k * HCP + c0];
            float vmv[4] = {vm.x, vm.y, vm.z, vm.w};
            float vav[4] = {va.x, va.y, va.z, va.w};
#pragma unroll
            for (int a = 0; a < 4; a++)
#pragma unroll
                for (int b = 0; b < 4; b++)
                    p[a][b] = fmaf(vmv[a], vav[b], p[a][b]);
        }

        // relu + r-scale, store transposed for stage 2
#pragma unroll
        for (int a = 0; a < 4; a++) {
            float sc = Rs[rr * TMP + m0 + a];
#pragma unroll
            for (int b = 0; b < 4; b++)
                Ps[(c0 + b) * TMP + (m0 + a)] = fmaxf(p[a][b], 0.f) * sc;
        }
        __syncthreads();

        // ---- stage 2: OUT += P @ W2^T, K = HC ----
#pragma unroll 8
        for (int k = 0; k < HC; k++) {
            float4 pm = *(const float4*)&Ps[k * TMP + m0];
            float4 wv = *(const float4*)&W2T[k * XDP + c0];
            float pmv[4] = {pm.x, pm.y, pm.z, pm.w};
            float wvv[4] = {wv.x, wv.y, wv.z, wv.w};
#pragma unroll
            for (int a = 0; a < 4; a++)
#pragma unroll
                for (int b = 0; b < 4; b++)
                    oacc[a][b] = fmaf(pmv[a], wvv[b], oacc[a][b]);
        }
    }

    // epilogue: two h-half CTAs accumulate into each output element
#pragma unroll
    for (int a = 0; a < 4; a++)
#pragma unroll
        for (int b = 0; b < 4; b++)
            atomicAdd(&out[(n * IJ + token0 + m0 + a) * XD + c0 + b], oacc[a][b]);
}

// ---------------------------------------------------------------------------
extern "C" void kernel_launch(void* const* d_in, const int* in_sizes, int n_in,
                              void* d_out, int out_size) {
    const float* r  = (const float*)d_in[0];
    const float* u  = (const float*)d_in[1];
    const float* v  = (const float*)d_in[2];
    const float* w1 = (const float*)d_in[3];
    const float* w2 = (const float*)d_in[4];
    float* out = (float*)d_out;
    (void)in_sizes; (void)n_in;

    cudaFuncSetAttribute(kernB, cudaFuncAttributeMaxDynamicSharedMemorySize, SMEM_B);

    kzero<<<(out_size + 255) / 256, 256>>>(out, out_size);
    kernA<<<dim3(RD, VD), 128>>>(u, w1);
    kernB<<<dim3(16, NB, 2), 256, SMEM_B>>>(v, r, w2, out);
}

// round 2
// speedup vs baseline: 1.1955x; 1.1955x over previous
#include <cuda_runtime.h>

#define RD 64
#define UD 64
#define VD 64
#define HD 128
#define XD 64
#define NB 8
#define IJ 1024          // 32*32 tokens per batch

// Kernel-B tiling: token tile 64, h-chunk 64 (HD split across blockIdx.z)
#define TM 64
#define HC 64
#define VSP 68           // Vs row stride (16B aligned rows)
#define RSP 68
#define ACP 68
#define W2P 65           // 65 makes the transposed store conflict-free
#define PSP 66

#define SM_FLOATS (VD*VSP + RD*RSP + VD*ACP + HC*W2P + HC*PSP)
#define SMEM_B (SM_FLOATS * (int)sizeof(float))

// Scratch: A[n][r][v][h] = sum_u w1[r,u,v,h] * u[n,r,u,v]   (16.8 MB, L2-resident)
__device__ float g_A[NB * RD * VD * HD];

typedef unsigned long long u64;

__device__ __forceinline__ u64 pk2(float lo, float hi) {
    u64 r; asm("mov.b64 %0,{%1,%2};" : "=l"(r) : "f"(lo), "f"(hi)); return r;
}
__device__ __forceinline__ u64 dup2(float v) {
    u64 r; asm("mov.b64 %0,{%1,%1};" : "=l"(r) : "f"(v)); return r;
}
__device__ __forceinline__ void fma2(u64& d, u64 a, u64 b) {
    asm("fma.rn.f32x2 %0,%1,%2,%0;" : "+l"(d) : "l"(a), "l"(b));
}
__device__ __forceinline__ u64 mul2(u64 a, u64 b) {
    u64 r; asm("mul.rn.f32x2 %0,%1,%2;" : "=l"(r) : "l"(a), "l"(b)); return r;
}
__device__ __forceinline__ void upk(u64 v, float& lo, float& hi) {
    asm("mov.b64 {%0,%1},%2;" : "=f"(lo), "=f"(hi) : "l"(v));
}

// ---------------------------------------------------------------------------
// Kernel A: contract u-axis; also zeroes the output (poisoned by harness).
// grid (RD, VD), 128 threads over h. w1 read exactly once, coalesced.
// ---------------------------------------------------------------------------
__global__ __launch_bounds__(128) void kernA(const float* __restrict__ u,
                                             const float* __restrict__ w1,
                                             float* __restrict__ out) {
    const int rr = blockIdx.x;
    const int vv = blockIdx.y;
    const int h  = threadIdx.x;

    // zero one output float per thread: 4096 CTAs * 128 = 524288 = out size
    out[(blockIdx.y * RD + blockIdx.x) * 128 + threadIdx.x] = 0.f;

    __shared__ float us[NB][UD];
    for (int idx = threadIdx.x; idx < NB * UD; idx += 128) {
        int n = idx >> 6, uu = idx & 63;
        us[n][uu] = u[((n * RD + rr) * UD + uu) * VD + vv];
    }
    __syncthreads();

    float acc[NB];
#pragma unroll
    for (int n = 0; n < NB; n++) acc[n] = 0.f;

    const float* w1p = w1 + (rr * UD * VD + vv) * HD + h;
#pragma unroll 4
    for (int uu = 0; uu < UD; uu++) {
        float w = w1p[uu * (VD * HD)];
#pragma unroll
        for (int n = 0; n < NB; n++) acc[n] = fmaf(w, us[n][uu], acc[n]);
    }
#pragma unroll
    for (int n = 0; n < NB; n++)
        g_A[((n * RD + rr) * VD + vv) * HD + h] = acc[n];
}

// ---------------------------------------------------------------------------
// Kernel B: fused double GEMM per (token tile, n, h-half), packed f32x2 FMAs.
//   stage1: P[m,h] = relu( sum_v V[m,v]*A[n,rr,v,h] ) * r[m,rr]
//   stage2: OUT[m,x] += sum_h P[m,h] * w2[x,rr,h]
// 128 threads; microtiles 8m x 4h (stage1) and 8m x 4x (stage2), m packed in pairs.
// ---------------------------------------------------------------------------
extern __shared__ float smem[];

__global__ __launch_bounds__(128, 2) void kernB(const float* __restrict__ v,
                                                const float* __restrict__ r,
                                                const float* __restrict__ w2,
                                                float* __restrict__ out) {
    const int tile   = blockIdx.x;          // 0..15
    const int n      = blockIdx.y;          // 0..7
    const int hblk   = blockIdx.z;          // 0..1
    const int token0 = tile * TM;
    const int tid    = threadIdx.x;
    const int mi = tid >> 4, ni = tid & 15;
    const int m0 = mi * 8, c0 = ni * 4;

    float* Vs  = smem;                      // [VD][VSP]  V^T:  [v][m]
    float* Rs  = Vs  + VD * VSP;            // [RD][RSP]  r^T:  [rr][m]
    float* Ach = Rs  + RD * RSP;            // [VD][ACP]  A:    [v][h]
    float* W2T = Ach + VD * ACP;            // [HC][W2P]  w2^T: [h][x]
    float* Ps  = W2T + HC * W2P;            // [HC][PSP]  P^T:  [h][m]

    for (int idx = tid; idx < TM * VD; idx += 128) {
        int m = idx >> 6, k = idx & 63;
        Vs[k * VSP + m] = v[(n * IJ + token0 + m) * VD + k];
        Rs[k * RSP + m] = r[(n * IJ + token0 + m) * RD + k];
    }

    u64 o2[4][4];
#pragma unroll
    for (int a = 0; a < 4; a++)
#pragma unroll
        for (int b = 0; b < 4; b++) o2[a][b] = 0ull;

    const int h0g = hblk * HC;
    const float* Abase = g_A + (n * RD * VD) * HD;

    for (int rr = 0; rr < RD; rr++) {
        __syncthreads();   // previous iteration's consumers done
        {
            const float* Ab = Abase + rr * VD * HD + h0g;
#pragma unroll 8
            for (int i = 0; i < 32; i++) {
                int idx = tid + i * 128;
                int k = idx >> 6, hh = idx & 63;
                Ach[k * ACP + hh] = Ab[k * HD + hh];
            }
            const float* Wb = w2 + rr * HD + h0g;
#pragma unroll 8
            for (int i = 0; i < 32; i++) {
                int idx = tid + i * 128;
                int x = idx >> 6, hh = idx & 63;
                W2T[hh * W2P + x] = Wb[x * (RD * HD) + hh];
            }
        }
        __syncthreads();

        // ---- stage 1: P tile (64m x 64h), K = VD, 8m(4 pairs) x 4h / thread ----
        u64 p2[4][4];
#pragma unroll
        for (int a = 0; a < 4; a++)
#pragma unroll
            for (int b = 0; b < 4; b++) p2[a][b] = 0ull;

#pragma unroll 8
        for (int k = 0; k < VD; k++) {
            const float* vrow = &Vs[k * VSP + m0];
            ulonglong2 vA = *(const ulonglong2*)(vrow);
            ulonglong2 vB = *(const ulonglong2*)(vrow + 4);
            u64 pa[4] = {vA.x, vA.y, vB.x, vB.y};
            float4 aa = *(const float4*)&Ach[k * ACP + c0];
            u64 b0 = dup2(aa.x), b1 = dup2(aa.y), b2 = dup2(aa.z), b3 = dup2(aa.w);
#pragma unroll
            for (int a = 0; a < 4; a++) {
                fma2(p2[a][0], pa[a], b0);
                fma2(p2[a][1], pa[a], b1);
                fma2(p2[a][2], pa[a], b2);
                fma2(p2[a][3], pa[a], b3);
            }
        }

        // relu + r-scale, store transposed (pairs along m) for stage 2
        {
            const float* rrow = &Rs[rr * RSP + m0];
            ulonglong2 rA = *(const ulonglong2*)(rrow);
            ulonglong2 rB = *(const ulonglong2*)(rrow + 4);
            u64 rp[4] = {rA.x, rA.y, rB.x, rB.y};
#pragma unroll
            for (int a = 0; a < 4; a++)
#pragma unroll
                for (int b = 0; b < 4; b++) {
                    float lo, hi; upk(p2[a][b], lo, hi);
                    lo = fmaxf(lo, 0.f); hi = fmaxf(hi, 0.f);
                    u64 s = mul2(pk2(lo, hi), rp[a]);
                    *(u64*)&Ps[(c0 + b) * PSP + m0 + 2 * a] = s;
                }
        }
        __syncthreads();

        // ---- stage 2: OUT += P @ W2^T, K = HC, 8m(4 pairs) x 4x / thread ----
#pragma unroll 8
        for (int k = 0; k < HC; k++) {
            const float* prow = &Ps[k * PSP + m0];
            u64 q0 = *(const u64*)(prow);
            u64 q1 = *(const u64*)(prow + 2);
            u64 q2 = *(const u64*)(prow + 4);
            u64 q3 = *(const u64*)(prow + 6);
            u64 qa[4] = {q0, q1, q2, q3};
            const float* wrow = &W2T[k * W2P + c0];
            u64 b0 = dup2(wrow[0]), b1 = dup2(wrow[1]), b2 = dup2(wrow[2]), b3 = dup2(wrow[3]);
#pragma unroll
            for (int a = 0; a < 4; a++) {
                fma2(o2[a][0], qa[a], b0);
                fma2(o2[a][1], qa[a], b1);
                fma2(o2[a][2], qa[a], b2);
                fma2(o2[a][3], qa[a], b3);
            }
        }
    }

    // epilogue: two h-half CTAs accumulate into each output element
#pragma unroll
    for (int a = 0; a < 4; a++)
#pragma unroll
        for (int b = 0; b < 4; b++) {
            float lo, hi; upk(o2[a][b], lo, hi);
            int m = n * IJ + token0 + m0 + 2 * a;
            atomicAdd(&out[m * XD + c0 + b], lo);
            atomicAdd(&out[(m + 1) * XD + c0 + b], hi);
        }
}

// ---------------------------------------------------------------------------
extern "C" void kernel_launch(void* const* d_in, const int* in_sizes, int n_in,
                              void* d_out, int out_size) {
    const float* r  = (const float*)d_in[0];
    const float* u  = (const float*)d_in[1];
    const float* v  = (const float*)d_in[2];
    const float* w1 = (const float*)d_in[3];
    const float* w2 = (const float*)d_in[4];
    float* out = (float*)d_out;
    (void)in_sizes; (void)n_in; (void)out_size;

    cudaFuncSetAttribute(kernB, cudaFuncAttributeMaxDynamicSharedMemorySize, SMEM_B);

    kernA<<<dim3(RD, VD), 128>>>(u, w1, out);
    kernB<<<dim3(16, NB, 2), 128, SMEM_B>>>(v, r, w2, out);
}